// round 5
// baseline (speedup 1.0000x reference)
#include <cuda_runtime.h>
#include <math.h>

#define B_ 1024
#define T_ 256
#define U_ 512
#define G4U (4 * U_)
#define P_ 32

#define BM 64      // batch tile per block
#define BU 32      // units tile per block (x4 gates)
#define KC 32      // K chunk
#define NTHREADS 256
#define NUT (U_ / BU)   // 16 u-tiles

// Persistent scratch (device globals = sanctioned; no allocations).
// h is stored TRANSPOSED: g_h[buf][u * B_ + b]  -> step-kernel H-tile loads
// are straight coalesced copies (no scatter).
__device__ float  g_h[2][U_ * B_];
__device__ float  g_c[B_ * U_];              // cell state, [b][u] layout
// Pre-interleaved Wh: [ut][k][64] float2 ; slots 0..31 = {Wi,Wf}(u), 32..63 = {Wg,Wo}(u)
__device__ float2 g_Whp[NUT * U_ * 64];

typedef unsigned long long ull;

// ---------------------------------------------------------------------------
// f32x2 packed-FMA helpers (Blackwell): 2 fp32 FMAs per instruction.
// ---------------------------------------------------------------------------
__device__ __forceinline__ ull pack2(float x) {
    ull r;
    asm("mov.b64 %0, {%1, %1};" : "=l"(r) : "f"(x));
    return r;
}
__device__ __forceinline__ void fma2(ull& acc, ull a, ull b) {
    asm("fma.rn.f32x2 %0, %1, %2, %0;" : "+l"(acc) : "l"(a), "l"(b));
}
__device__ __forceinline__ float fast_tanh(float x) {
    float y;
    asm("tanh.approx.f32 %0, %1;" : "=f"(y) : "f"(x));
    return y;
}
__device__ __forceinline__ float fast_sigmoid(float z) {
    // sigmoid(z) = 0.5 * tanh(z/2) + 0.5  (single MUFU-class op)
    return fmaf(0.5f, fast_tanh(0.5f * z), 0.5f);
}

// ---------------------------------------------------------------------------
// Zero initial state.
// ---------------------------------------------------------------------------
__global__ void zero_state_kernel() {
    int i = blockIdx.x * blockDim.x + threadIdx.x;
    if (i < B_ * U_) {
        g_h[0][i] = 0.0f;
        g_c[i]    = 0.0f;
    }
}

// ---------------------------------------------------------------------------
// One-shot Wh re-layout: gate-interleaved float2 pairs, chunk-contiguous, so
// the step kernel's W-tile load is a pure coalesced float4 copy.
// ---------------------------------------------------------------------------
__global__ void prep_w_kernel(const float* __restrict__ Wh) {
    int idx = blockIdx.x * blockDim.x + threadIdx.x;   // < 16*512*64
    if (idx >= NUT * U_ * 64) return;
    int slot = idx & 63;
    int k    = (idx >> 6) & (U_ - 1);
    int ut   = idx >> 15;
    int half = slot >> 5;           // 0: {i,f}  1: {g,o}
    int j    = slot & 31;
    int u    = ut * BU + j;
    float2 v;
    v.x = Wh[k * G4U + (half * 2 + 0) * U_ + u];
    v.y = Wh[k * G4U + (half * 2 + 1) * U_ + u];
    g_Whp[idx] = v;
}

// ---------------------------------------------------------------------------
// One LSTM step. Grid (16,16)=256 blocks, 256 threads, 2 blocks/SM.
// warp -> 8 batch rows, lane -> unit u0+lane. Accumulators are f32x2 over
// gate pairs (i,f)/(g,o); W loads as natural float2 from smem; h is a
// warp-uniform broadcast packed via mov.b64 on the ALU pipe.
// ---------------------------------------------------------------------------
__global__ void __launch_bounds__(NTHREADS, 2)
lstm_step_kernel(const float* __restrict__ prices, int t,
                 const float* __restrict__ Wx,
                 const float* __restrict__ bias) {
    __shared__ float                Hs[KC][BM];     // [k][b]
    __shared__ __align__(16) float2 W2[KC][64];     // [k][slot]

    const int tid  = threadIdx.x;
    const int lane = tid & 31;
    const int warp = tid >> 5;              // 0..7
    const int b0   = blockIdx.x * BM;
    const int ut   = blockIdx.y;
    const int u0   = ut * BU;
    const int bb   = warp * 8;

    const float* __restrict__ h_in  = g_h[t & 1];
    float* __restrict__       h_out = g_h[(t + 1) & 1];

    ull acc_if[8], acc_go[8];
#pragma unroll
    for (int i = 0; i < 8; i++) { acc_if[i] = 0ull; acc_go[i] = 0ull; }

    for (int kc = 0; kc < U_; kc += KC) {
        // H tile: straight coalesced copy (h is transposed in gmem)
#pragma unroll
        for (int i = 0; i < 2; i++) {
            int q  = tid + i * NTHREADS;        // 0..511 float4 units
            int k  = q >> 4;
            int b4 = (q & 15) << 2;
            *reinterpret_cast<float4*>(&Hs[k][b4]) =
                *reinterpret_cast<const float4*>(&h_in[(kc + k) * B_ + b0 + b4]);
        }
        // W tile: contiguous 16KB copy from pre-interleaved layout
        {
            const float4* wsrc = reinterpret_cast<const float4*>(
                g_Whp + ((size_t)ut * U_ + kc) * 64);
            float4* wdst = reinterpret_cast<float4*>(&W2[0][0]);
#pragma unroll
            for (int i = 0; i < 4; i++)
                wdst[tid + i * NTHREADS] = wsrc[tid + i * NTHREADS];
        }
        __syncthreads();

#pragma unroll 8
        for (int k = 0; k < KC; k++) {
            float4 h03 = *reinterpret_cast<const float4*>(&Hs[k][bb]);
            float4 h47 = *reinterpret_cast<const float4*>(&Hs[k][bb + 4]);
            ull wif = *reinterpret_cast<const ull*>(&W2[k][lane]);
            ull wgo = *reinterpret_cast<const ull*>(&W2[k][32 + lane]);
            float hv[8] = {h03.x, h03.y, h03.z, h03.w,
                           h47.x, h47.y, h47.z, h47.w};
#pragma unroll
            for (int i = 0; i < 8; i++) {
                ull hp = pack2(hv[i]);
                fma2(acc_if[i], hp, wif);
                fma2(acc_go[i], hp, wgo);
            }
        }
        __syncthreads();
    }

    // ---- epilogue: gates, c update, h (with smem transpose for coalesced
    //      transposed h_out writes) ----
    const int u = u0 + lane;
    const float wx0 = Wx[0 * U_ + u], wx1 = Wx[1 * U_ + u];
    const float wx2 = Wx[2 * U_ + u], wx3 = Wx[3 * U_ + u];
    const float bv0 = bias[0 * U_ + u], bv1 = bias[1 * U_ + u];
    const float bv2 = bias[2 * U_ + u], bv3 = bias[3 * U_ + u];

    float hval[8];
#pragma unroll
    for (int i = 0; i < 8; i++) {
        int b = b0 + bb + i;
        float x = prices[b * T_ + t];
        union { ull u64; float2 f; } cif, cgo;
        cif.u64 = acc_if[i];
        cgo.u64 = acc_go[i];
        float zi = fmaf(x, wx0, cif.f.x + bv0);
        float zf = fmaf(x, wx1, cif.f.y + bv1);
        float zg = fmaf(x, wx2, cgo.f.x + bv2);
        float zo = fmaf(x, wx3, cgo.f.y + bv3);
        float ig = fast_sigmoid(zi);
        float fg = fast_sigmoid(zf);
        float gg = fast_tanh(zg);
        float og = fast_sigmoid(zo);
        int cidx = b * U_ + u;                   // coalesced over lanes
        float c = fmaf(fg, g_c[cidx], ig * gg);
        g_c[cidx] = c;
        hval[i] = og * fast_tanh(c);
    }

    // transpose 64b x 32u through smem (stride 65 -> conflict-free STS)
    float* Tt = reinterpret_cast<float*>(&W2[0][0]);   // needs 32*65 floats
#pragma unroll
    for (int i = 0; i < 8; i++)
        Tt[lane * 65 + bb + i] = hval[i];
    __syncthreads();
    {
        int up = tid >> 3;                 // 0..31
        int bp = (tid & 7) * 8;            // 0..56
        float4 v0, v1;
        v0.x = Tt[up * 65 + bp + 0]; v0.y = Tt[up * 65 + bp + 1];
        v0.z = Tt[up * 65 + bp + 2]; v0.w = Tt[up * 65 + bp + 3];
        v1.x = Tt[up * 65 + bp + 4]; v1.y = Tt[up * 65 + bp + 5];
        v1.z = Tt[up * 65 + bp + 6]; v1.w = Tt[up * 65 + bp + 7];
        float* dst = &h_out[(u0 + up) * B_ + b0 + bp];
        *reinterpret_cast<float4*>(dst)     = v0;
        *reinterpret_cast<float4*>(dst + 4) = v1;
    }
}

// ---------------------------------------------------------------------------
// Head: out = relu(h @ Wd + bd) @ Wp + bp.  Final h is in g_h[0], transposed.
// ---------------------------------------------------------------------------
__global__ void head_kernel(const float* __restrict__ Wd,
                            const float* __restrict__ bd,
                            const float* __restrict__ Wp,
                            const float* __restrict__ bp,
                            float* __restrict__ out) {
    __shared__ float xs[64];
    int b = blockIdx.x;
    int j = threadIdx.x;                      // 0..63
    float s = bd[j];
#pragma unroll 8
    for (int k = 0; k < U_; k++)
        s = fmaf(g_h[0][k * B_ + b], Wd[k * 64 + j], s);  // h warp-uniform
    xs[j] = fmaxf(s, 0.0f);
    __syncthreads();
    if (j < P_) {
        float s2 = bp[j];
#pragma unroll
        for (int k = 0; k < 64; k++)
            s2 = fmaf(xs[k], Wp[k * P_ + j], s2);
        out[b * P_ + j] = s2;
    }
}

// ---------------------------------------------------------------------------
// kernel_launch: zero + prep, 256 step kernels, head. Graph-capturable.
// ---------------------------------------------------------------------------
extern "C" void kernel_launch(void* const* d_in, const int* in_sizes, int n_in,
                              void* d_out, int out_size) {
    const float* prices = (const float*)d_in[0];  // [B, T]
    const float* Wx     = (const float*)d_in[1];  // [1, 4U]
    const float* Wh     = (const float*)d_in[2];  // [U, 4U]
    const float* bias   = (const float*)d_in[3];  // [4U]
    const float* Wd     = (const float*)d_in[4];  // [U, 64]
    const float* bd     = (const float*)d_in[5];  // [64]
    const float* Wp     = (const float*)d_in[6];  // [64, P]
    const float* bp     = (const float*)d_in[7];  // [P]
    float* out          = (float*)d_out;          // [B, P]

    (void)in_sizes; (void)n_in; (void)out_size;

    zero_state_kernel<<<(B_ * U_ + 255) / 256, 256>>>();
    prep_w_kernel<<<(NUT * U_ * 64 + 255) / 256, 256>>>(Wh);

    dim3 grid(B_ / BM, NUT);                      // (16, 16) = 256 blocks
    for (int t = 0; t < T_; t++) {
        lstm_step_kernel<<<grid, NTHREADS>>>(prices, t, Wx, bias);
    }

    head_kernel<<<B_, 64>>>(Wd, bd, Wp, bp, out);
}

// round 6
// speedup vs baseline: 1.0022x; 1.0022x over previous
#include <cuda_runtime.h>
#include <math.h>

#define B_ 1024
#define T_ 256
#define U_ 512
#define G4U (4 * U_)
#define P_ 32

#define BM 64      // batch tile per block
#define BU 32      // units tile per block (x4 gates)
#define KC 32      // K chunk
#define NTHREADS 256
#define NUT (U_ / BU)   // 16 u-tiles

// Persistent scratch (device globals = sanctioned; no allocations).
// h is stored TRANSPOSED: g_h[buf][u * B_ + b]  -> step-kernel H-tile loads
// are straight coalesced copies (no scatter).
__device__ float  g_h[2][U_ * B_];
__device__ float  g_c[B_ * U_];              // cell state, [b][u] layout
// Pre-interleaved Wh: [ut][k][64] float2 ; slots 0..31 = {Wi,Wf}(u), 32..63 = {Wg,Wo}(u)
__device__ float2 g_Whp[NUT * U_ * 64];

typedef unsigned long long ull;

// ---------------------------------------------------------------------------
// f32x2 packed-FMA helpers (Blackwell): 2 fp32 FMAs per instruction.
// ---------------------------------------------------------------------------
__device__ __forceinline__ ull pack2(float x) {
    ull r;
    asm("mov.b64 %0, {%1, %1};" : "=l"(r) : "f"(x));
    return r;
}
__device__ __forceinline__ void fma2(ull& acc, ull a, ull b) {
    asm("fma.rn.f32x2 %0, %1, %2, %0;" : "+l"(acc) : "l"(a), "l"(b));
}
__device__ __forceinline__ float fast_tanh(float x) {
    float y;
    asm("tanh.approx.f32 %0, %1;" : "=f"(y) : "f"(x));
    return y;
}
__device__ __forceinline__ float fast_sigmoid(float z) {
    // sigmoid(z) = 0.5 * tanh(z/2) + 0.5  (single MUFU-class op)
    return fmaf(0.5f, fast_tanh(0.5f * z), 0.5f);
}

// ---------------------------------------------------------------------------
// Zero initial state.
// ---------------------------------------------------------------------------
__global__ void zero_state_kernel() {
    int i = blockIdx.x * blockDim.x + threadIdx.x;
    if (i < B_ * U_) {
        g_h[0][i] = 0.0f;
        g_c[i]    = 0.0f;
    }
}

// ---------------------------------------------------------------------------
// One-shot Wh re-layout: gate-interleaved float2 pairs, chunk-contiguous, so
// the step kernel's W-tile load is a pure coalesced float4 copy.
// ---------------------------------------------------------------------------
__global__ void prep_w_kernel(const float* __restrict__ Wh) {
    int idx = blockIdx.x * blockDim.x + threadIdx.x;   // < 16*512*64
    if (idx >= NUT * U_ * 64) return;
    int slot = idx & 63;
    int k    = (idx >> 6) & (U_ - 1);
    int ut   = idx >> 15;
    int half = slot >> 5;           // 0: {i,f}  1: {g,o}
    int j    = slot & 31;
    int u    = ut * BU + j;
    float2 v;
    v.x = Wh[k * G4U + (half * 2 + 0) * U_ + u];
    v.y = Wh[k * G4U + (half * 2 + 1) * U_ + u];
    g_Whp[idx] = v;
}

// ---------------------------------------------------------------------------
// One LSTM step. Grid (16,16)=256 blocks, 256 threads, 2 blocks/SM.
// warp -> 8 batch rows, lane -> unit u0+lane. Accumulators are f32x2 over
// gate pairs (i,f)/(g,o); W loads as natural float2 from smem; h is a
// warp-uniform broadcast packed via mov.b64 on the ALU pipe.
// ---------------------------------------------------------------------------
__global__ void __launch_bounds__(NTHREADS, 2)
lstm_step_kernel(const float* __restrict__ prices, int t,
                 const float* __restrict__ Wx,
                 const float* __restrict__ bias) {
    __shared__ float                Hs[KC][BM];     // [k][b]
    __shared__ __align__(16) float2 W2[KC][64];     // [k][slot]

    const int tid  = threadIdx.x;
    const int lane = tid & 31;
    const int warp = tid >> 5;              // 0..7
    const int b0   = blockIdx.x * BM;
    const int ut   = blockIdx.y;
    const int u0   = ut * BU;
    const int bb   = warp * 8;

    const float* __restrict__ h_in  = g_h[t & 1];
    float* __restrict__       h_out = g_h[(t + 1) & 1];

    ull acc_if[8], acc_go[8];
#pragma unroll
    for (int i = 0; i < 8; i++) { acc_if[i] = 0ull; acc_go[i] = 0ull; }

    for (int kc = 0; kc < U_; kc += KC) {
        // H tile: straight coalesced copy (h is transposed in gmem)
#pragma unroll
        for (int i = 0; i < 2; i++) {
            int q  = tid + i * NTHREADS;        // 0..511 float4 units
            int k  = q >> 4;
            int b4 = (q & 15) << 2;
            *reinterpret_cast<float4*>(&Hs[k][b4]) =
                *reinterpret_cast<const float4*>(&h_in[(kc + k) * B_ + b0 + b4]);
        }
        // W tile: contiguous 16KB copy from pre-interleaved layout
        {
            const float4* wsrc = reinterpret_cast<const float4*>(
                g_Whp + ((size_t)ut * U_ + kc) * 64);
            float4* wdst = reinterpret_cast<float4*>(&W2[0][0]);
#pragma unroll
            for (int i = 0; i < 4; i++)
                wdst[tid + i * NTHREADS] = wsrc[tid + i * NTHREADS];
        }
        __syncthreads();

#pragma unroll 8
        for (int k = 0; k < KC; k++) {
            float4 h03 = *reinterpret_cast<const float4*>(&Hs[k][bb]);
            float4 h47 = *reinterpret_cast<const float4*>(&Hs[k][bb + 4]);
            ull wif = *reinterpret_cast<const ull*>(&W2[k][lane]);
            ull wgo = *reinterpret_cast<const ull*>(&W2[k][32 + lane]);
            float hv[8] = {h03.x, h03.y, h03.z, h03.w,
                           h47.x, h47.y, h47.z, h47.w};
#pragma unroll
            for (int i = 0; i < 8; i++) {
                ull hp = pack2(hv[i]);
                fma2(acc_if[i], hp, wif);
                fma2(acc_go[i], hp, wgo);
            }
        }
        __syncthreads();
    }

    // ---- epilogue: gates, c update, h (with smem transpose for coalesced
    //      transposed h_out writes) ----
    const int u = u0 + lane;
    const float wx0 = Wx[0 * U_ + u], wx1 = Wx[1 * U_ + u];
    const float wx2 = Wx[2 * U_ + u], wx3 = Wx[3 * U_ + u];
    const float bv0 = bias[0 * U_ + u], bv1 = bias[1 * U_ + u];
    const float bv2 = bias[2 * U_ + u], bv3 = bias[3 * U_ + u];

    float hval[8];
#pragma unroll
    for (int i = 0; i < 8; i++) {
        int b = b0 + bb + i;
        float x = prices[b * T_ + t];
        union { ull u64; float2 f; } cif, cgo;
        cif.u64 = acc_if[i];
        cgo.u64 = acc_go[i];
        float zi = fmaf(x, wx0, cif.f.x + bv0);
        float zf = fmaf(x, wx1, cif.f.y + bv1);
        float zg = fmaf(x, wx2, cgo.f.x + bv2);
        float zo = fmaf(x, wx3, cgo.f.y + bv3);
        float ig = fast_sigmoid(zi);
        float fg = fast_sigmoid(zf);
        float gg = fast_tanh(zg);
        float og = fast_sigmoid(zo);
        int cidx = b * U_ + u;                   // coalesced over lanes
        float c = fmaf(fg, g_c[cidx], ig * gg);
        g_c[cidx] = c;
        hval[i] = og * fast_tanh(c);
    }

    // transpose 64b x 32u through smem (stride 65 -> conflict-free STS)
    float* Tt = reinterpret_cast<float*>(&W2[0][0]);   // needs 32*65 floats
#pragma unroll
    for (int i = 0; i < 8; i++)
        Tt[lane * 65 + bb + i] = hval[i];
    __syncthreads();
    {
        int up = tid >> 3;                 // 0..31
        int bp = (tid & 7) * 8;            // 0..56
        float4 v0, v1;
        v0.x = Tt[up * 65 + bp + 0]; v0.y = Tt[up * 65 + bp + 1];
        v0.z = Tt[up * 65 + bp + 2]; v0.w = Tt[up * 65 + bp + 3];
        v1.x = Tt[up * 65 + bp + 4]; v1.y = Tt[up * 65 + bp + 5];
        v1.z = Tt[up * 65 + bp + 6]; v1.w = Tt[up * 65 + bp + 7];
        float* dst = &h_out[(u0 + up) * B_ + b0 + bp];
        *reinterpret_cast<float4*>(dst)     = v0;
        *reinterpret_cast<float4*>(dst + 4) = v1;
    }
}

// ---------------------------------------------------------------------------
// Head: out = relu(h @ Wd + bd) @ Wp + bp.  Final h is in g_h[0], transposed.
// ---------------------------------------------------------------------------
__global__ void head_kernel(const float* __restrict__ Wd,
                            const float* __restrict__ bd,
                            const float* __restrict__ Wp,
                            const float* __restrict__ bp,
                            float* __restrict__ out) {
    __shared__ float xs[64];
    int b = blockIdx.x;
    int j = threadIdx.x;                      // 0..63
    float s = bd[j];
#pragma unroll 8
    for (int k = 0; k < U_; k++)
        s = fmaf(g_h[0][k * B_ + b], Wd[k * 64 + j], s);  // h warp-uniform
    xs[j] = fmaxf(s, 0.0f);
    __syncthreads();
    if (j < P_) {
        float s2 = bp[j];
#pragma unroll
        for (int k = 0; k < 64; k++)
            s2 = fmaf(xs[k], Wp[k * P_ + j], s2);
        out[b * P_ + j] = s2;
    }
}

// ---------------------------------------------------------------------------
// kernel_launch: zero + prep, 256 step kernels, head. Graph-capturable.
// ---------------------------------------------------------------------------
extern "C" void kernel_launch(void* const* d_in, const int* in_sizes, int n_in,
                              void* d_out, int out_size) {
    const float* prices = (const float*)d_in[0];  // [B, T]
    const float* Wx     = (const float*)d_in[1];  // [1, 4U]
    const float* Wh     = (const float*)d_in[2];  // [U, 4U]
    const float* bias   = (const float*)d_in[3];  // [4U]
    const float* Wd     = (const float*)d_in[4];  // [U, 64]
    const float* bd     = (const float*)d_in[5];  // [64]
    const float* Wp     = (const float*)d_in[6];  // [64, P]
    const float* bp     = (const float*)d_in[7];  // [P]
    float* out          = (float*)d_out;          // [B, P]

    (void)in_sizes; (void)n_in; (void)out_size;

    zero_state_kernel<<<(B_ * U_ + 255) / 256, 256>>>();
    prep_w_kernel<<<(NUT * U_ * 64 + 255) / 256, 256>>>(Wh);

    dim3 grid(B_ / BM, NUT);                      // (16, 16) = 256 blocks
    for (int t = 0; t < T_; t++) {
        lstm_step_kernel<<<grid, NTHREADS>>>(prices, t, Wx, bias);
    }

    head_kernel<<<B_, 64>>>(Wd, bd, Wp, bp, out);
}